// round 15
// baseline (speedup 1.0000x reference)
#include <cuda_runtime.h>
#include <math.h>
#include <stdint.h>

// Problem constants
namespace {
constexpr int kB    = 4;
constexpr int kLQ   = 1024;
constexpr int kD    = 2048;
constexpr int kH    = 16;
constexpr int kG    = 4;
constexpr int kHD   = 128;
constexpr int kPAST = 1024;
constexpr int kLK   = 2048;
constexpr int kM    = kB * kLQ;          // 4096
constexpr int kNQ   = kD;                // 2048
constexpr int kNKV  = kG * kHD;          // 512
constexpr int kNTOT = kNQ + 2 * kNKV;    // 3072
constexpr float kScaleL2E = 0.08838834764831845f * 1.4426950408889634f;
}

// Scratch (tf32 bit patterns)
__device__ uint32_t g_q  [kB * kH * kLQ * kHD];   // pre-scaled by kScale*log2e
__device__ uint32_t g_kc [kB * kG * kLK * kHD];   // (b,g,p,d)
__device__ uint32_t g_vt [kB * kG * kHD * kLK];   // (b,g,d,p)  TRANSPOSED
__device__ uint32_t g_att[kB * kLQ * kD];
__device__ uint32_t g_x  [kM * kD];               // [m][k]
__device__ uint32_t g_wqT[kNQ  * kD];             // [n][k] transposed
__device__ uint32_t g_wkT[kNKV * kD];
__device__ uint32_t g_wvT[kNKV * kD];
__device__ uint32_t g_woT[kD   * kD];

// ---------------------------------------------------------------------------
// helpers
// ---------------------------------------------------------------------------
__device__ __forceinline__ uint32_t f2tf(float f) {
    uint32_t r;
    asm("cvt.rna.tf32.f32 %0, %1;" : "=r"(r) : "f"(f));
    return r;
}
__device__ __forceinline__ float ex2(float x) {
    float r;
    asm("ex2.approx.f32 %0, %1;" : "=f"(r) : "f"(x));
    return r;
}
__device__ __forceinline__ void mma_tf32(float* c, const uint32_t* a, const uint32_t* b) {
    asm volatile(
        "mma.sync.aligned.m16n8k8.row.col.f32.tf32.tf32.f32 "
        "{%0,%1,%2,%3}, {%4,%5,%6,%7}, {%8,%9}, {%0,%1,%2,%3};"
        : "+f"(c[0]), "+f"(c[1]), "+f"(c[2]), "+f"(c[3])
        : "r"(a[0]), "r"(a[1]), "r"(a[2]), "r"(a[3]), "r"(b[0]), "r"(b[1]));
}
__device__ __forceinline__ uint4 cvt4(float4 v) {
    return make_uint4(f2tf(v.x), f2tf(v.y), f2tf(v.z), f2tf(v.w));
}
__device__ __forceinline__ uint32_t s2u(const void* p) {
    return (uint32_t)__cvta_generic_to_shared(p);
}
__device__ __forceinline__ void cp16(uint32_t saddr, const void* gptr) {
    asm volatile("cp.async.cg.shared.global [%0], [%1], 16;"
                 :: "r"(saddr), "l"(gptr));
}
__device__ __forceinline__ void cp_commit() {
    asm volatile("cp.async.commit_group;" ::: "memory");
}
template <int N>
__device__ __forceinline__ void cp_wait() {
    asm volatile("cp.async.wait_group %0;" :: "n"(N) : "memory");
}
__device__ __forceinline__ void ldsm_x4(uint32_t* r, uint32_t saddr) {
    asm volatile("ldmatrix.sync.aligned.m8n8.x4.shared.b16 {%0,%1,%2,%3}, [%4];"
        : "=r"(r[0]), "=r"(r[1]), "=r"(r[2]), "=r"(r[3]) : "r"(saddr));
}
__device__ __forceinline__ void ldsm_x2(uint32_t* r, uint32_t saddr) {
    asm volatile("ldmatrix.sync.aligned.m8n8.x2.shared.b16 {%0,%1}, [%2];"
        : "=r"(r[0]), "=r"(r[1]) : "r"(saddr));
}

// ---------------------------------------------------------------------------
// Kernel 0a: convert x to tf32 (row-major)
// ---------------------------------------------------------------------------
__global__ void cvt_x_kernel(const float4* __restrict__ x) {
    int i = blockIdx.x * blockDim.x + threadIdx.x;
    if (i < kM * kD / 4) ((uint4*)g_x)[i] = cvt4(x[i]);
}

// ---------------------------------------------------------------------------
// Kernel 0b: transpose-convert a weight matrix W[k][n] -> WT[n][k] tf32.
// Destination selected by `which` INSIDE device code.
// ---------------------------------------------------------------------------
__global__ void cvt_wt_kernel(const float* __restrict__ W, int N, int which) {
    uint32_t* WT = (which == 0) ? g_wqT
                 : (which == 1) ? g_wkT
                 : (which == 2) ? g_wvT : g_woT;
    __shared__ float t[32][33];
    const int n0 = blockIdx.x * 32;
    const int k0 = blockIdx.y * 32;
    const int tx = threadIdx.x, ty = threadIdx.y;
#pragma unroll
    for (int r = 0; r < 4; r++)
        t[ty + r * 8][tx] = W[(size_t)(k0 + ty + r * 8) * N + n0 + tx];
    __syncthreads();
#pragma unroll
    for (int r = 0; r < 4; r++)
        WT[(size_t)(n0 + ty + r * 8) * kD + k0 + tx] = f2tf(t[tx][ty + r * 8]);
}

// ---------------------------------------------------------------------------
// Kernel 1: copy past K (straight) + past V (transposed) into caches
// ---------------------------------------------------------------------------
__global__ void copy_past_kernel(const float* __restrict__ pk,
                                 const float* __restrict__ pv) {
    __shared__ float t[32][33];
    const int bg = blockIdx.z;
    const int p0 = blockIdx.y * 32;
    const int d0 = blockIdx.x * 32;
    const int tx = threadIdx.x, ty = threadIdx.y;
#pragma unroll
    for (int r = 0; r < 4; r++) {
        int p = p0 + ty + r * 8;
        size_t src = ((size_t)bg * kPAST + p) * kHD + d0 + tx;
        g_kc[((size_t)bg * kLK + p) * kHD + d0 + tx] = f2tf(pk[src]);
        t[ty + r * 8][tx] = pv[src];
    }
    __syncthreads();
#pragma unroll
    for (int r = 0; r < 4; r++) {
        int d = d0 + ty + r * 8;
        g_vt[((size_t)bg * kHD + d) * kLK + p0 + tx] = f2tf(t[tx][ty + r * 8]);
    }
}

// ---------------------------------------------------------------------------
// GEMM pipeline: 128x128x32, 3-stage cp.async, 2 CTAs/SM, ldmatrix frags.
// ---------------------------------------------------------------------------
constexpr int A_ST  = 36;
constexpr int BT_ST = 36;
constexpr int STG_A = 128 * A_ST;
constexpr int STG_B = 128 * BT_ST;
constexpr int STG_W = STG_A + STG_B;
constexpr int NSTG  = 3;
constexpr int GEMM_SMEM = NSTG * STG_W * 4;   // 110,592 B

// ---------------------------------------------------------------------------
// Kernel 2: QKV projection GEMM + bias + RoPE + tf32 scatter
// ---------------------------------------------------------------------------
__global__ __launch_bounds__(256, 2) void qkv_kernel(
    const float* __restrict__ rf,
    const float* __restrict__ bq, const float* __restrict__ bk,
    const float* __restrict__ bv) {

    extern __shared__ uint32_t smw[];

    const int n0  = blockIdx.x * 128;
    const int m0  = blockIdx.y * 128;
    const int tid = threadIdx.x;
    const int wid = tid >> 5, lane = tid & 31;
    const int wm = (wid >> 2) * 64;
    const int wn = (wid & 3) * 32;
    const int ln4 = lane >> 2, lc4 = lane & 3;
    const int lx  = lane & 15, lxt = (lane >> 4) << 2;
    const int ly  = lane & 7,  lyt = ((lane >> 3) & 1) << 2;

    const uint32_t* WT; const float* bias; int nloc; int seg;
    if (n0 < kNQ)              { WT = g_wqT; bias = bq; nloc = n0;              seg = 0; }
    else if (n0 < kNQ + kNKV)  { WT = g_wkT; bias = bk; nloc = n0 - kNQ;        seg = 1; }
    else                       { WT = g_wvT; bias = bv; nloc = n0 - kNQ - kNKV; seg = 2; }

    auto load_stage = [&](int s, int k0) {
        uint32_t* As = smw + s * STG_W;
        uint32_t* Bs = As + STG_A;
#pragma unroll
        for (int it = 0; it < 4; it++) {
            int idx = tid + it * 256;
            int m = idx >> 3, q = idx & 7;
            cp16(s2u(&As[m * A_ST + q * 4]),
                 &g_x[(size_t)(m0 + m) * kD + k0 + q * 4]);
        }
#pragma unroll
        for (int it = 0; it < 4; it++) {
            int idx = tid + it * 256;
            int n = idx >> 3, q = idx & 7;
            cp16(s2u(&Bs[n * BT_ST + q * 4]),
                 &WT[(size_t)(nloc + n) * kD + k0 + q * 4]);
        }
    };

    float acc[4][4][4] = {};

#pragma unroll
    for (int s = 0; s < NSTG; s++) { load_stage(s, s * 32); cp_commit(); }

    const int KT = kD / 32;
    for (int ki = 0; ki < KT; ki++) {
        cp_wait<NSTG - 1>();
        __syncthreads();
        const uint32_t as_b = s2u(smw + (ki % NSTG) * STG_W);
        const uint32_t bs_b = as_b + STG_A * 4;
#pragma unroll
        for (int k8 = 0; k8 < 32; k8 += 8) {
            uint32_t a[4][4], bb[4][2];
#pragma unroll
            for (int mf = 0; mf < 4; mf++)
                ldsm_x4(a[mf], as_b + ((wm + mf * 16 + lx) * A_ST + k8 + lxt) * 4);
#pragma unroll
            for (int nf = 0; nf < 4; nf++)
                ldsm_x2(bb[nf], bs_b + ((wn + nf * 8 + ly) * BT_ST + k8 + lyt) * 4);
#pragma unroll
            for (int mf = 0; mf < 4; mf++)
#pragma unroll
                for (int nf = 0; nf < 4; nf++)
                    mma_tf32(acc[mf][nf], a[mf], bb[nf]);
        }
        __syncthreads();
        int kn = ki + NSTG;
        if (kn < KT) load_stage(ki % NSTG, kn * 32);
        cp_commit();
    }

    // Epilogue: bias + RoPE + tf32 scatter
#pragma unroll
    for (int mf = 0; mf < 4; mf++) {
#pragma unroll
        for (int rp = 0; rp < 2; rp++) {
            const int m = m0 + wm + mf * 16 + ln4 + rp * 8;
            const int b = m >> 10;
            const int t = m & (kLQ - 1);
#pragma unroll
            for (int nf = 0; nf < 4; nf++) {
                const int n = nloc + wn + nf * 8 + lc4 * 2;
                float v0 = acc[mf][nf][rp * 2 + 0] + bias[n];
                float v1 = acc[mf][nf][rp * 2 + 1] + bias[n + 1];
                const int d = n & 127;
                if (seg == 0) {
                    const int h = n >> 7;
                    float sn, cs; sincosf(rf[t * (kHD / 2) + (d >> 1)], &sn, &cs);
                    float r0 = v0 * cs - v1 * sn;
                    float r1 = v0 * sn + v1 * cs;
                    uint32_t* dst = &g_q[((size_t)((b * kH + h) * kLQ + t) * kHD) + d];
                    *(uint2*)dst = make_uint2(f2tf(r0 * kScaleL2E), f2tf(r1 * kScaleL2E));
                } else if (seg == 1) {
                    const int g = n >> 7;
                    float sn, cs; sincosf(rf[t * (kHD / 2) + (d >> 1)], &sn, &cs);
                    float r0 = v0 * cs - v1 * sn;
                    float r1 = v0 * sn + v1 * cs;
                    uint32_t* dst = &g_kc[((size_t)((b * kG + g) * kLK + kPAST + t) * kHD) + d];
                    *(uint2*)dst = make_uint2(f2tf(r0), f2tf(r1));
                } else {
                    const int g = n >> 7;
                    size_t base = ((size_t)(b * kG + g) * kHD + d) * kLK + kPAST + t;
                    g_vt[base]       = f2tf(v0);
                    g_vt[base + kLK] = f2tf(v1);
                }
            }
        }
    }
}

// ---------------------------------------------------------------------------
// Kernel 3: flash attention — serial phases, BQ=64, BK=32, 128 threads
// (4 warps: 2m x 2n), 2 CTAs/SM. Max-free softmax via ex2.
// ---------------------------------------------------------------------------
constexpr int QS_ST = 132;   // [t][d]
constexpr int KK_ST = 132;   // [key][d]
constexpr int VT_ST = 36;    // [d][key]
constexpr int PS_ST = 36;    // [row][key]
constexpr int ATTN_WORDS = 64 * QS_ST + 32 * KK_ST + 128 * VT_ST + 64 * PS_ST + 2 * 64;
constexpr int ATTN_SMEM_BYTES = ATTN_WORDS * 4;   // 79,360 B (x2 CTAs = 155 KB)

__global__ __launch_bounds__(128, 2) void attn_kernel() {
    extern __shared__ uint32_t smw[];
    uint32_t* Qs = smw;
    uint32_t* Kb = Qs + 64 * QS_ST;
    uint32_t* Vt = Kb + 32 * KK_ST;
    uint32_t* Ps = Vt + 128 * VT_ST;
    float*   red = (float*)(Ps + 64 * PS_ST);   // [2 wn2][64 rows]

    const int qb = blockIdx.x;
    const int h  = blockIdx.y;
    const int b  = blockIdx.z;
    const int g  = h >> 2;
    const int t0 = qb * 64;
    const int tid = threadIdx.x;
    const int wid = tid >> 5, lane = tid & 31;
    const int wm2 = wid >> 1;         // 0..1 (m half: 32 rows)
    const int wn2 = wid & 1;          // 0..1 (key/d half)
    const int arow = wm2 * 32;
    const int ln4 = lane >> 2, lc4 = lane & 3;
    const int lx  = lane & 15, lxt = (lane >> 4) << 2;
    const int ly  = lane & 7,  lyt = ((lane >> 3) & 1) << 2;

    const uint32_t qs_b = s2u(Qs), kb_b = s2u(Kb), vt_b = s2u(Vt), ps_b = s2u(Ps);

    const uint32_t* qbase  = g_q  + ((size_t)(b * kH + h) * kLQ + t0) * kHD;
    const uint32_t* kbase  = g_kc + (size_t)(b * kG + g) * kLK * kHD;
    const uint32_t* vtbase = g_vt + (size_t)(b * kG + g) * kHD * kLK;

    // Prologue: Q tile (64 rows x 32 float4) + K(0) (32 rows x 32 float4)
#pragma unroll
    for (int it = 0; it < 16; it++) {
        int idx = tid + it * 128;
        int t = idx >> 5, q = idx & 31;
        cp16(qs_b + (t * QS_ST + q * 4) * 4, &qbase[(size_t)t * kHD + q * 4]);
    }
#pragma unroll
    for (int it = 0; it < 8; it++) {
        int idx = tid + it * 128;
        int key = idx >> 5, q = idx & 31;
        cp16(kb_b + (key * KK_ST + q * 4) * 4, &kbase[(size_t)key * kHD + q * 4]);
    }
    cp_commit();

    float oacc[2][8][4] = {};
    float l_i[4] = {0.f, 0.f, 0.f, 0.f};

    const int ntiles = (kPAST + t0) / 32 + 2;

    for (int kt = 0; kt < ntiles; kt++) {
        const int k0 = kt * 32;
        cp_wait<0>();
        __syncthreads();       // K(kt) visible; prev O-mma done with Vt

        // stream V(kt): 128 d-rows x 32 keys (8 float4 per row)
#pragma unroll
        for (int it = 0; it < 8; it++) {
            int idx = tid + it * 128;
            int row = idx >> 3, c = (idx & 7) << 2;
            cp16(vt_b + (row * VT_ST + c) * 4,
                 &vtbase[(size_t)row * kLK + k0 + c]);
        }
        cp_commit();

        // S = Q.K^T  — warp tile m32 x n16, k=128
        float sacc[2][2][4] = {};
#pragma unroll
        for (int k8 = 0; k8 < 16; k8++) {
            const int d0 = k8 * 8;
            uint32_t a[2][4], bb[2][2];
#pragma unroll
            for (int mf2 = 0; mf2 < 2; mf2++)
                ldsm_x4(a[mf2], qs_b + ((arow + mf2 * 16 + lx) * QS_ST + d0 + lxt) * 4);
#pragma unroll
            for (int nf = 0; nf < 2; nf++)
                ldsm_x2(bb[nf], kb_b + ((wn2 * 16 + nf * 8 + ly) * KK_ST + d0 + lyt) * 4);
#pragma unroll
            for (int mf2 = 0; mf2 < 2; mf2++)
#pragma unroll
                for (int nf = 0; nf < 2; nf++)
                    mma_tf32(sacc[mf2][nf], a[mf2], bb[nf]);
        }

        // causal mask near diagonal
        if (k0 + 31 > kPAST + t0) {
#pragma unroll
            for (int mf2 = 0; mf2 < 2; mf2++) {
                const int qpos0 = kPAST + t0 + arow + mf2 * 16 + ln4;
#pragma unroll
                for (int nf = 0; nf < 2; nf++)
#pragma unroll
                    for (int j = 0; j < 2; j++) {
                        int kpos = k0 + wn2 * 16 + nf * 8 + lc4 * 2 + j;
                        if (kpos > qpos0)     sacc[mf2][nf][j]     = -1e30f;
                        if (kpos > qpos0 + 8) sacc[mf2][nf][2 + j] = -1e30f;
                    }
            }
        }

        // ---- max-free softmax: p = ex2(s), local l accumulate, store P ----
#pragma unroll
        for (int mf2 = 0; mf2 < 2; mf2++)
#pragma unroll
            for (int nf = 0; nf < 2; nf++) {
                float p0 = ex2(sacc[mf2][nf][0]);
                float p1 = ex2(sacc[mf2][nf][1]);
                float p2 = ex2(sacc[mf2][nf][2]);
                float p3 = ex2(sacc[mf2][nf][3]);
                l_i[mf2 * 2 + 0] += p0 + p1;
                l_i[mf2 * 2 + 1] += p2 + p3;
                int col = wn2 * 16 + nf * 8 + lc4 * 2;
                *(uint2*)&Ps[(arow + mf2 * 16 + ln4) * PS_ST + col] =
                    make_uint2(f2tf(p0), f2tf(p1));
                *(uint2*)&Ps[(arow + mf2 * 16 + ln4 + 8) * PS_ST + col] =
                    make_uint2(f2tf(p2), f2tf(p3));
            }

        cp_wait<0>();          // V(kt) complete (only pending group)
        __syncthreads();       // V + Ps visible; all Kb reads retired

        // prefetch K(kt+1) during O-phase (32 rows x 32 float4)
        if (kt + 1 < ntiles) {
            int kn0 = k0 + 32;
#pragma unroll
            for (int it = 0; it < 8; it++) {
                int idx = tid + it * 128;
                int key = idx >> 5, q = idx & 31;
                cp16(kb_b + (key * KK_ST + q * 4) * 4,
                     &kbase[(size_t)(kn0 + key) * kHD + q * 4]);
            }
        }
        cp_commit();

        // O += P.V — warp tile m32 x n64 (d-cols wn2*64..), k=32
#pragma unroll
        for (int kk8 = 0; kk8 < 4; kk8++) {
            const int kk0 = kk8 * 8;
            uint32_t a[2][4], bb[8][2];
#pragma unroll
            for (int mf2 = 0; mf2 < 2; mf2++)
                ldsm_x4(a[mf2], ps_b + ((arow + mf2 * 16 + lx) * PS_ST + kk0 + lxt) * 4);
#pragma unroll
            for (int nf = 0; nf < 8; nf++)
                ldsm_x2(bb[nf], vt_b + ((wn2 * 64 + nf * 8 + ly) * VT_ST + kk0 + lyt) * 4);
#pragma unroll
            for (int mf2 = 0; mf2 < 2; mf2++)
#pragma unroll
                for (int nf = 0; nf < 8; nf++)
                    mma_tf32(oacc[mf2][nf], a[mf2], bb[nf]);
        }
    }

    // ---- epilogue: reduce l across lanes + key-half warps, then store ----
#pragma unroll
    for (int i = 0; i < 4; i++) {
        l_i[i] += __shfl_xor_sync(0xffffffffu, l_i[i], 1);
        l_i[i] += __shfl_xor_sync(0xffffffffu, l_i[i], 2);
    }
    if (lc4 == 0) {
#pragma unroll
        for (int i = 0; i < 4; i++)
            red[wn2 * 64 + arow + (i >> 1) * 16 + (i & 1) * 8 + ln4] = l_i[i];
    }
    __syncthreads();
#pragma unroll
    for (int i = 0; i < 4; i++) {
        int row = arow + (i >> 1) * 16 + (i & 1) * 8 + ln4;
        l_i[i] += red[(wn2 ^ 1) * 64 + row];
    }

#pragma unroll
    for (int mf2 = 0; mf2 < 2; mf2++) {
        const float inv0 = 1.f / l_i[mf2 * 2];
        const float inv1 = 1.f / l_i[mf2 * 2 + 1];
        const int rowA = t0 + arow + mf2 * 16 + ln4;
        uint32_t* dA = &g_att[((size_t)(b * kLQ + rowA)) * kD + h * kHD];
        uint32_t* dB = &g_att[((size_t)(b * kLQ + rowA + 8)) * kD + h * kHD];
#pragma unroll
        for (int nf = 0; nf < 8; nf++) {
            int col = wn2 * 64 + nf * 8 + lc4 * 2;
            *(uint2*)&dA[col] = make_uint2(f2tf(oacc[mf2][nf][0] * inv0),
                                           f2tf(oacc[mf2][nf][1] * inv0));
            *(uint2*)&dB[col] = make_uint2(f2tf(oacc[mf2][nf][2] * inv1),
                                           f2tf(oacc[mf2][nf][3] * inv1));
        }
    }
}

// ---------------------------------------------------------------------------
// Kernel 4: output GEMM (A = g_att, B = g_woT), ldmatrix, 3-stage, 2 CTA/SM
// ---------------------------------------------------------------------------
__global__ __launch_bounds__(256, 2) void out_kernel(
    const float* __restrict__ bo, float* __restrict__ out) {

    extern __shared__ uint32_t smw[];

    const int n0  = blockIdx.x * 128;
    const int m0  = blockIdx.y * 128;
    const int tid = threadIdx.x;
    const int wid = tid >> 5, lane = tid & 31;
    const int wm = (wid >> 2) * 64;
    const int wn = (wid & 3) * 32;
    const int ln4 = lane >> 2, lc4 = lane & 3;
    const int lx  = lane & 15, lxt = (lane >> 4) << 2;
    const int ly  = lane & 7,  lyt = ((lane >> 3) & 1) << 2;

    auto load_stage = [&](int s, int k0) {
        uint32_t* As = smw + s * STG_W;
        uint32_t* Bs = As + STG_A;
#pragma unroll
        for (int it = 0; it < 4; it++) {
            int idx = tid + it * 256;
            int m = idx >> 3, q = idx & 7;
            cp16(s2u(&As[m * A_ST + q * 4]),
                 &g_att[(size_t)(m0 + m) * kD + k0 + q * 4]);
        }
#pragma unroll
        for (int it = 0; it < 4; it++) {
            int idx = tid + it * 256;
            int n = idx >> 3, q = idx & 7;
            cp16(s2u(&Bs[n * BT_ST + q * 4]),
                 &g_woT[(size_t)(n0 + n) * kD + k0 + q * 4]);
        }
    };

    float acc[4][4][4] = {};

#pragma unroll
    for (int s = 0; s < NSTG; s++) { load_stage(s, s * 32); cp_commit(); }

    const int KT = kD / 32;
    for (int ki = 0; ki < KT; ki++) {
        cp_wait<NSTG - 1>();
        __syncthreads();
        const uint32_t as_b = s2u(smw + (ki % NSTG) * STG_W);
        const uint32_t bs_b = as_b + STG_A * 4;
#pragma unroll
        for (int k8 = 0; k8 < 32; k8 += 8) {
            uint32_t a[4][4], bb[4][2];
#pragma unroll
            for (int mf = 0; mf < 4; mf++)
                ldsm_x4(a[mf], as_b + ((wm + mf * 16 + lx) * A_ST + k8 + lxt) * 4);
#pragma unroll
            for (int nf = 0; nf < 4; nf++)
                ldsm_x2(bb[nf], bs_b + ((wn + nf * 8 + ly) * BT_ST + k8 + lyt) * 4);
#pragma unroll
            for (int mf = 0; mf < 4; mf++)
#pragma unroll
                for (int nf = 0; nf < 4; nf++)
                    mma_tf32(acc[mf][nf], a[mf], bb[nf]);
        }
        __syncthreads();
        int kn = ki + NSTG;
        if (kn < KT) load_stage(ki % NSTG, kn * 32);
        cp_commit();
    }

#pragma unroll
    for (int mf = 0; mf < 4; mf++) {
#pragma unroll
        for (int rp = 0; rp < 2; rp++) {
            const int m = m0 + wm + mf * 16 + ln4 + rp * 8;
#pragma unroll
            for (int nf = 0; nf < 4; nf++) {
                const int n = n0 + wn + nf * 8 + lc4 * 2;
                float v0 = acc[mf][nf][rp * 2 + 0] + bo[n];
                float v1 = acc[mf][nf][rp * 2 + 1] + bo[n + 1];
                *(float2*)&out[(size_t)m * kD + n] = make_float2(v0, v1);
            }
        }
    }
}

// ---------------------------------------------------------------------------
// Launch
// ---------------------------------------------------------------------------
extern "C" void kernel_launch(void* const* d_in, const int* in_sizes, int n_in,
                              void* d_out, int out_size) {
    const float* x  = (const float*)d_in[0];
    const float* rf = (const float*)d_in[2];
    const float* pk = (const float*)d_in[3];
    const float* pv = (const float*)d_in[4];
    const float* Wq = (const float*)d_in[5];
    const float* bq = (const float*)d_in[6];
    const float* Wk = (const float*)d_in[7];
    const float* bk = (const float*)d_in[8];
    const float* Wv = (const float*)d_in[9];
    const float* bv = (const float*)d_in[10];
    const float* Wo = (const float*)d_in[11];
    const float* bo = (const float*)d_in[12];
    float* out = (float*)d_out;

    cudaFuncSetAttribute(qkv_kernel,  cudaFuncAttributeMaxDynamicSharedMemorySize, GEMM_SMEM);
    cudaFuncSetAttribute(out_kernel,  cudaFuncAttributeMaxDynamicSharedMemorySize, GEMM_SMEM);
    cudaFuncSetAttribute(attn_kernel, cudaFuncAttributeMaxDynamicSharedMemorySize, ATTN_SMEM_BYTES);

    cvt_x_kernel<<<(kM * kD / 4 + 255) / 256, 256>>>((const float4*)x);
    cvt_wt_kernel<<<dim3(kNQ / 32,  kD / 32), dim3(32, 8)>>>(Wq, kNQ,  0);
    cvt_wt_kernel<<<dim3(kNKV / 32, kD / 32), dim3(32, 8)>>>(Wk, kNKV, 1);
    cvt_wt_kernel<<<dim3(kNKV / 32, kD / 32), dim3(32, 8)>>>(Wv, kNKV, 2);
    cvt_wt_kernel<<<dim3(kD / 32,   kD / 32), dim3(32, 8)>>>(Wo, kD,   3);
    copy_past_kernel<<<dim3(kHD / 32, kPAST / 32, kB * kG), dim3(32, 8)>>>(pk, pv);
    qkv_kernel<<<dim3(kNTOT / 128, kM / 128), 256, GEMM_SMEM>>>(rf, bq, bk, bv);
    attn_kernel<<<dim3(kLQ / 64, kH, kB), 128, ATTN_SMEM_BYTES>>>();
    out_kernel<<<dim3(kD / 128, kM / 128), 256, GEMM_SMEM>>>(bo, out);
}

// round 16
// speedup vs baseline: 1.0059x; 1.0059x over previous
#include <cuda_runtime.h>
#include <math.h>
#include <stdint.h>

// Problem constants
namespace {
constexpr int kB    = 4;
constexpr int kLQ   = 1024;
constexpr int kD    = 2048;
constexpr int kH    = 16;
constexpr int kG    = 4;
constexpr int kHD   = 128;
constexpr int kPAST = 1024;
constexpr int kLK   = 2048;
constexpr int kM    = kB * kLQ;          // 4096
constexpr int kNQ   = kD;                // 2048
constexpr int kNKV  = kG * kHD;          // 512
constexpr int kNTOT = kNQ + 2 * kNKV;    // 3072
constexpr float kScaleL2E = 0.08838834764831845f * 1.4426950408889634f;
}

// Scratch (tf32 bit patterns)
__device__ uint32_t g_q  [kB * kH * kLQ * kHD];   // pre-scaled by kScale*log2e
__device__ uint32_t g_kc [kB * kG * kLK * kHD];   // (b,g,p,d)
__device__ uint32_t g_vt [kB * kG * kHD * kLK];   // (b,g,d,p)  TRANSPOSED
__device__ uint32_t g_att[kB * kLQ * kD];
__device__ uint32_t g_x  [kM * kD];               // [m][k]
__device__ uint32_t g_wqT[kNQ  * kD];             // [n][k] transposed
__device__ uint32_t g_wkT[kNKV * kD];
__device__ uint32_t g_wvT[kNKV * kD];
__device__ uint32_t g_woT[kD   * kD];

// ---------------------------------------------------------------------------
// helpers
// ---------------------------------------------------------------------------
__device__ __forceinline__ uint32_t f2tf(float f) {
    uint32_t r;
    asm("cvt.rna.tf32.f32 %0, %1;" : "=r"(r) : "f"(f));
    return r;
}
__device__ __forceinline__ float ex2(float x) {
    float r;
    asm("ex2.approx.f32 %0, %1;" : "=f"(r) : "f"(x));
    return r;
}
__device__ __forceinline__ void mma_tf32(float* c, const uint32_t* a, const uint32_t* b) {
    asm volatile(
        "mma.sync.aligned.m16n8k8.row.col.f32.tf32.tf32.f32 "
        "{%0,%1,%2,%3}, {%4,%5,%6,%7}, {%8,%9}, {%0,%1,%2,%3};"
        : "+f"(c[0]), "+f"(c[1]), "+f"(c[2]), "+f"(c[3])
        : "r"(a[0]), "r"(a[1]), "r"(a[2]), "r"(a[3]), "r"(b[0]), "r"(b[1]));
}
__device__ __forceinline__ uint4 cvt4(float4 v) {
    return make_uint4(f2tf(v.x), f2tf(v.y), f2tf(v.z), f2tf(v.w));
}
__device__ __forceinline__ uint32_t s2u(const void* p) {
    return (uint32_t)__cvta_generic_to_shared(p);
}
__device__ __forceinline__ void cp16(uint32_t saddr, const void* gptr) {
    asm volatile("cp.async.cg.shared.global [%0], [%1], 16;"
                 :: "r"(saddr), "l"(gptr));
}
__device__ __forceinline__ void cp_commit() {
    asm volatile("cp.async.commit_group;" ::: "memory");
}
template <int N>
__device__ __forceinline__ void cp_wait() {
    asm volatile("cp.async.wait_group %0;" :: "n"(N) : "memory");
}
__device__ __forceinline__ void ldsm_x4(uint32_t* r, uint32_t saddr) {
    asm volatile("ldmatrix.sync.aligned.m8n8.x4.shared.b16 {%0,%1,%2,%3}, [%4];"
        : "=r"(r[0]), "=r"(r[1]), "=r"(r[2]), "=r"(r[3]) : "r"(saddr));
}
__device__ __forceinline__ void ldsm_x2(uint32_t* r, uint32_t saddr) {
    asm volatile("ldmatrix.sync.aligned.m8n8.x2.shared.b16 {%0,%1}, [%2];"
        : "=r"(r[0]), "=r"(r[1]) : "r"(saddr));
}

// ---------------------------------------------------------------------------
// Kernel 0a: convert x to tf32 (row-major)
// ---------------------------------------------------------------------------
__global__ void cvt_x_kernel(const float4* __restrict__ x) {
    int i = blockIdx.x * blockDim.x + threadIdx.x;
    if (i < kM * kD / 4) ((uint4*)g_x)[i] = cvt4(x[i]);
}

// ---------------------------------------------------------------------------
// Kernel 0b: transpose-convert a weight matrix W[k][n] -> WT[n][k] tf32.
// Destination selected by `which` INSIDE device code.
// ---------------------------------------------------------------------------
__global__ void cvt_wt_kernel(const float* __restrict__ W, int N, int which) {
    uint32_t* WT = (which == 0) ? g_wqT
                 : (which == 1) ? g_wkT
                 : (which == 2) ? g_wvT : g_woT;
    __shared__ float t[32][33];
    const int n0 = blockIdx.x * 32;
    const int k0 = blockIdx.y * 32;
    const int tx = threadIdx.x, ty = threadIdx.y;
#pragma unroll
    for (int r = 0; r < 4; r++)
        t[ty + r * 8][tx] = W[(size_t)(k0 + ty + r * 8) * N + n0 + tx];
    __syncthreads();
#pragma unroll
    for (int r = 0; r < 4; r++)
        WT[(size_t)(n0 + ty + r * 8) * kD + k0 + tx] = f2tf(t[tx][ty + r * 8]);
}

// ---------------------------------------------------------------------------
// Kernel 1: copy past K (straight) + past V (transposed) into caches
// ---------------------------------------------------------------------------
__global__ void copy_past_kernel(const float* __restrict__ pk,
                                 const float* __restrict__ pv) {
    __shared__ float t[32][33];
    const int bg = blockIdx.z;
    const int p0 = blockIdx.y * 32;
    const int d0 = blockIdx.x * 32;
    const int tx = threadIdx.x, ty = threadIdx.y;
#pragma unroll
    for (int r = 0; r < 4; r++) {
        int p = p0 + ty + r * 8;
        size_t src = ((size_t)bg * kPAST + p) * kHD + d0 + tx;
        g_kc[((size_t)bg * kLK + p) * kHD + d0 + tx] = f2tf(pk[src]);
        t[ty + r * 8][tx] = pv[src];
    }
    __syncthreads();
#pragma unroll
    for (int r = 0; r < 4; r++) {
        int d = d0 + ty + r * 8;
        g_vt[((size_t)bg * kHD + d) * kLK + p0 + tx] = f2tf(t[tx][ty + r * 8]);
    }
}

// ---------------------------------------------------------------------------
// GEMM pipeline: 128x128x32, 3-stage cp.async, 2 CTAs/SM, ldmatrix frags.
// Single barrier per k-iter; loads for stage ki+2 issued BEFORE consumption
// (target buffer (ki-1)%3 is free once this iteration's barrier passes).
// ---------------------------------------------------------------------------
constexpr int A_ST  = 36;
constexpr int BT_ST = 36;
constexpr int STG_A = 128 * A_ST;
constexpr int STG_B = 128 * BT_ST;
constexpr int STG_W = STG_A + STG_B;
constexpr int NSTG  = 3;
constexpr int GEMM_SMEM = NSTG * STG_W * 4;   // 110,592 B

// ---------------------------------------------------------------------------
// Kernel 2: QKV projection GEMM + bias + RoPE + tf32 scatter
// ---------------------------------------------------------------------------
__global__ __launch_bounds__(256, 2) void qkv_kernel(
    const float* __restrict__ rf,
    const float* __restrict__ bq, const float* __restrict__ bk,
    const float* __restrict__ bv) {

    extern __shared__ uint32_t smw[];

    const int n0  = blockIdx.x * 128;
    const int m0  = blockIdx.y * 128;
    const int tid = threadIdx.x;
    const int wid = tid >> 5, lane = tid & 31;
    const int wm = (wid >> 2) * 64;
    const int wn = (wid & 3) * 32;
    const int ln4 = lane >> 2, lc4 = lane & 3;
    const int lx  = lane & 15, lxt = (lane >> 4) << 2;
    const int ly  = lane & 7,  lyt = ((lane >> 3) & 1) << 2;

    const uint32_t* WT; const float* bias; int nloc; int seg;
    if (n0 < kNQ)              { WT = g_wqT; bias = bq; nloc = n0;              seg = 0; }
    else if (n0 < kNQ + kNKV)  { WT = g_wkT; bias = bk; nloc = n0 - kNQ;        seg = 1; }
    else                       { WT = g_wvT; bias = bv; nloc = n0 - kNQ - kNKV; seg = 2; }

    auto load_stage = [&](int s, int k0) {
        uint32_t* As = smw + s * STG_W;
        uint32_t* Bs = As + STG_A;
#pragma unroll
        for (int it = 0; it < 4; it++) {
            int idx = tid + it * 256;
            int m = idx >> 3, q = idx & 7;
            cp16(s2u(&As[m * A_ST + q * 4]),
                 &g_x[(size_t)(m0 + m) * kD + k0 + q * 4]);
        }
#pragma unroll
        for (int it = 0; it < 4; it++) {
            int idx = tid + it * 256;
            int n = idx >> 3, q = idx & 7;
            cp16(s2u(&Bs[n * BT_ST + q * 4]),
                 &WT[(size_t)(nloc + n) * kD + k0 + q * 4]);
        }
    };

    float acc[4][4][4] = {};

    // Prologue: NSTG-1 stages in flight
#pragma unroll
    for (int s = 0; s < NSTG - 1; s++) { load_stage(s, s * 32); cp_commit(); }

    const int KT = kD / 32;
    for (int ki = 0; ki < KT; ki++) {
        cp_wait<NSTG - 2>();   // stage ki resident (stage ki+1 may be in flight)
        __syncthreads();       // all threads done with stage ki-1 -> its buffer is free
        int kn = ki + NSTG - 1;
        if (kn < KT) load_stage(kn % NSTG, kn * 32);
        cp_commit();

        const uint32_t as_b = s2u(smw + (ki % NSTG) * STG_W);
        const uint32_t bs_b = as_b + STG_A * 4;
#pragma unroll
        for (int k8 = 0; k8 < 32; k8 += 8) {
            uint32_t a[4][4], bb[4][2];
#pragma unroll
            for (int mf = 0; mf < 4; mf++)
                ldsm_x4(a[mf], as_b + ((wm + mf * 16 + lx) * A_ST + k8 + lxt) * 4);
#pragma unroll
            for (int nf = 0; nf < 4; nf++)
                ldsm_x2(bb[nf], bs_b + ((wn + nf * 8 + ly) * BT_ST + k8 + lyt) * 4);
#pragma unroll
            for (int mf = 0; mf < 4; mf++)
#pragma unroll
                for (int nf = 0; nf < 4; nf++)
                    mma_tf32(acc[mf][nf], a[mf], bb[nf]);
        }
    }

    // Epilogue: bias + RoPE + tf32 scatter
#pragma unroll
    for (int mf = 0; mf < 4; mf++) {
#pragma unroll
        for (int rp = 0; rp < 2; rp++) {
            const int m = m0 + wm + mf * 16 + ln4 + rp * 8;
            const int b = m >> 10;
            const int t = m & (kLQ - 1);
#pragma unroll
            for (int nf = 0; nf < 4; nf++) {
                const int n = nloc + wn + nf * 8 + lc4 * 2;
                float v0 = acc[mf][nf][rp * 2 + 0] + bias[n];
                float v1 = acc[mf][nf][rp * 2 + 1] + bias[n + 1];
                const int d = n & 127;
                if (seg == 0) {
                    const int h = n >> 7;
                    float sn, cs; sincosf(rf[t * (kHD / 2) + (d >> 1)], &sn, &cs);
                    float r0 = v0 * cs - v1 * sn;
                    float r1 = v0 * sn + v1 * cs;
                    uint32_t* dst = &g_q[((size_t)((b * kH + h) * kLQ + t) * kHD) + d];
                    *(uint2*)dst = make_uint2(f2tf(r0 * kScaleL2E), f2tf(r1 * kScaleL2E));
                } else if (seg == 1) {
                    const int g = n >> 7;
                    float sn, cs; sincosf(rf[t * (kHD / 2) + (d >> 1)], &sn, &cs);
                    float r0 = v0 * cs - v1 * sn;
                    float r1 = v0 * sn + v1 * cs;
                    uint32_t* dst = &g_kc[((size_t)((b * kG + g) * kLK + kPAST + t) * kHD) + d];
                    *(uint2*)dst = make_uint2(f2tf(r0), f2tf(r1));
                } else {
                    const int g = n >> 7;
                    size_t base = ((size_t)(b * kG + g) * kHD + d) * kLK + kPAST + t;
                    g_vt[base]       = f2tf(v0);
                    g_vt[base + kLK] = f2tf(v1);
                }
            }
        }
    }
}

// ---------------------------------------------------------------------------
// Kernel 3: flash attention — R12 structure (serial S -> exp -> O, single K
// buffer, f2tf P), max-free softmax via ex2 (Q pre-scaled by kScale*log2e).
// BQ=128, BK=64; 8 warps (4m x 2n); 2 barriers per K-tile.
// ---------------------------------------------------------------------------
constexpr int QS_ST = 132;   // [t][d]
constexpr int KK_ST = 132;   // [key][d]
constexpr int VT_ST = 68;    // [d][key]
constexpr int PS_ST = 68;    // [row][key]
constexpr int ATTN_WORDS = 128 * QS_ST + 64 * KK_ST + 128 * VT_ST + 128 * PS_ST + 2 * 128;
constexpr int ATTN_SMEM_BYTES = ATTN_WORDS * 4;   // 172,032 B

__global__ __launch_bounds__(256, 1) void attn_kernel() {
    extern __shared__ uint32_t smw[];
    uint32_t* Qs = smw;
    uint32_t* Kb = Qs + 128 * QS_ST;
    uint32_t* Vt = Kb + 64 * KK_ST;
    uint32_t* Ps = Vt + 128 * VT_ST;
    float*   red = (float*)(Ps + 128 * PS_ST);   // [2 wn2][128 rows]

    const int qb = blockIdx.x;
    const int h  = blockIdx.y;
    const int b  = blockIdx.z;
    const int g  = h >> 2;
    const int t0 = qb * 128;
    const int tid = threadIdx.x;
    const int wid = tid >> 5, lane = tid & 31;
    const int wm2 = wid >> 1;
    const int wn2 = wid & 1;
    const int arow = wm2 * 32;
    const int ln4 = lane >> 2, lc4 = lane & 3;
    const int lx  = lane & 15, lxt = (lane >> 4) << 2;
    const int ly  = lane & 7,  lyt = ((lane >> 3) & 1) << 2;

    const uint32_t qs_b = s2u(Qs), kb_b = s2u(Kb), vt_b = s2u(Vt), ps_b = s2u(Ps);

    const uint32_t* qbase  = g_q  + ((size_t)(b * kH + h) * kLQ + t0) * kHD;
    const uint32_t* kbase  = g_kc + (size_t)(b * kG + g) * kLK * kHD;
    const uint32_t* vtbase = g_vt + (size_t)(b * kG + g) * kHD * kLK;

    // Prologue: Q tile + K(0)
#pragma unroll
    for (int it = 0; it < 16; it++) {
        int idx = tid + it * 256;
        int t = idx >> 5, q = idx & 31;
        cp16(qs_b + (t * QS_ST + q * 4) * 4, &qbase[(size_t)t * kHD + q * 4]);
    }
#pragma unroll
    for (int it = 0; it < 8; it++) {
        int idx = tid + it * 256;
        int key = idx >> 5, q = idx & 31;
        cp16(kb_b + (key * KK_ST + q * 4) * 4, &kbase[(size_t)key * kHD + q * 4]);
    }
    cp_commit();

    float oacc[2][8][4] = {};
    float l_i[4] = {0.f, 0.f, 0.f, 0.f};

    const int ntiles = (kPAST + t0) / 64 + 2;

    for (int kt = 0; kt < ntiles; kt++) {
        const int k0 = kt * 64;
        cp_wait<0>();
        __syncthreads();       // K(kt) visible; prev O-mma done with Vt

        // stream V(kt): 128 d-rows x 64 keys (transposed layout)
#pragma unroll
        for (int it = 0; it < 8; it++) {
            int idx = tid + it * 256;
            int row = idx >> 4, c = (idx & 15) << 2;
            cp16(vt_b + (row * VT_ST + c) * 4,
                 &vtbase[(size_t)row * kLK + k0 + c]);
        }
        cp_commit();

        // S = Q.K^T  — warp tile m32 x n32, k=128
        float sacc[2][4][4] = {};
#pragma unroll
        for (int k8 = 0; k8 < 16; k8++) {
            const int d0 = k8 * 8;
            uint32_t a[2][4], bb[4][2];
#pragma unroll
            for (int mf2 = 0; mf2 < 2; mf2++)
                ldsm_x4(a[mf2], qs_b + ((arow + mf2 * 16 + lx) * QS_ST + d0 + lxt) * 4);
#pragma unroll
            for (int nf = 0; nf < 4; nf++)
                ldsm_x2(bb[nf], kb_b + ((wn2 * 32 + nf * 8 + ly) * KK_ST + d0 + lyt) * 4);
#pragma unroll
            for (int mf2 = 0; mf2 < 2; mf2++)
#pragma unroll
                for (int nf = 0; nf < 4; nf++)
                    mma_tf32(sacc[mf2][nf], a[mf2], bb[nf]);
        }

        // causal mask near diagonal
        if (k0 + 63 > kPAST + t0) {
#pragma unroll
            for (int mf2 = 0; mf2 < 2; mf2++) {
                const int qpos0 = kPAST + t0 + arow + mf2 * 16 + ln4;
#pragma unroll
                for (int nf = 0; nf < 4; nf++)
#pragma unroll
                    for (int j = 0; j < 2; j++) {
                        int kpos = k0 + wn2 * 32 + nf * 8 + lc4 * 2 + j;
                        if (kpos > qpos0)     sacc[mf2][nf][j]     = -1e30f;
                        if (kpos > qpos0 + 8) sacc[mf2][nf][2 + j] = -1e30f;
                    }
            }
        }

        // ---- max-free softmax: p = ex2(s), local l accumulate, store P ----
#pragma unroll
        for (int mf2 = 0; mf2 < 2; mf2++)
#pragma unroll
            for (int nf = 0; nf < 4; nf++) {
                float p0 = ex2(sacc[mf2][nf][0]);
                float p1 = ex2(sacc[mf2][nf][1]);
                float p2 = ex2(sacc[mf2][nf][2]);
                float p3 = ex2(sacc[mf2][nf][3]);
                l_i[mf2 * 2 + 0] += p0 + p1;
                l_i[mf2 * 2 + 1] += p2 + p3;
                int col = wn2 * 32 + nf * 8 + lc4 * 2;
                *(uint2*)&Ps[(arow + mf2 * 16 + ln4) * PS_ST + col] =
                    make_uint2(f2tf(p0), f2tf(p1));
                *(uint2*)&Ps[(arow + mf2 * 16 + ln4 + 8) * PS_ST + col] =
                    make_uint2(f2tf(p2), f2tf(p3));
            }

        cp_wait<0>();          // V(kt) complete (only pending group)
        __syncthreads();       // V + Ps visible; all Kb reads retired

        // prefetch K(kt+1) during O-phase
        if (kt + 1 < ntiles) {
            int kn0 = k0 + 64;
#pragma unroll
            for (int it = 0; it < 8; it++) {
                int idx = tid + it * 256;
                int key = idx >> 5, q = idx & 31;
                cp16(kb_b + (key * KK_ST + q * 4) * 4,
                     &kbase[(size_t)(kn0 + key) * kHD + q * 4]);
            }
        }
        cp_commit();

        // O += P.V — warp tile m32 x n64, k=64
#pragma unroll
        for (int kk8 = 0; kk8 < 8; kk8++) {
            const int kk0 = kk8 * 8;
            uint32_t a[2][4], bb[8][2];
#pragma unroll
            for (int mf2 = 0; mf2 < 2; mf2++)
                ldsm_x4(a[mf2], ps_b + ((arow + mf2 * 16 + lx) * PS_ST + kk0 + lxt) * 4);
#pragma unroll
            for (int nf = 0; nf < 8; nf++)
                ldsm_x2(bb[nf], vt_b + ((wn2 * 64 + nf * 8 + ly) * VT_ST + kk0 + lyt) * 4);
#pragma unroll
            for (int mf2 = 0; mf2 < 2; mf2++)
#pragma unroll
                for (int nf = 0; nf < 8; nf++)
                    mma_tf32(oacc[mf2][nf], a[mf2], bb[nf]);
        }
    }

    // ---- epilogue: reduce l across lanes + key-half warps, then store ----
#pragma unroll
    for (int i = 0; i < 4; i++) {
        l_i[i] += __shfl_xor_sync(0xffffffffu, l_i[i], 1);
        l_i[i] += __shfl_xor_sync(0xffffffffu, l_i[i], 2);
    }
    if (lc4 == 0) {
#pragma unroll
        for (int i = 0; i < 4; i++)
            red[wn2 * 128 + arow + (i >> 1) * 16 + (i & 1) * 8 + ln4] = l_i[i];
    }
    __syncthreads();
#pragma unroll
    for (int i = 0; i < 4; i++) {
        int row = arow + (i >> 1) * 16 + (i & 1) * 8 + ln4;
        l_i[i] += red[(wn2 ^ 1) * 128 + row];
    }

#pragma unroll
    for (int mf2 = 0; mf2 < 2; mf2++) {
        const float inv0 = 1.f / l_i[mf2 * 2];
        const float inv1 = 1.f / l_i[mf2 * 2 + 1];
        const int rowA = t0 + arow + mf2 * 16 + ln4;
        uint32_t* dA = &g_att[((size_t)(b * kLQ + rowA)) * kD + h * kHD];
        uint32_t* dB = &g_att[((size_t)(b * kLQ + rowA + 8)) * kD + h * kHD];
#pragma unroll
        for (int nf = 0; nf < 8; nf++) {
            int col = wn2 * 64 + nf * 8 + lc4 * 2;
            *(uint2*)&dA[col] = make_uint2(f2tf(oacc[mf2][nf][0] * inv0),
                                           f2tf(oacc[mf2][nf][1] * inv0));
            *(uint2*)&dB[col] = make_uint2(f2tf(oacc[mf2][nf][2] * inv1),
                                           f2tf(oacc[mf2][nf][3] * inv1));
        }
    }
}

// ---------------------------------------------------------------------------
// Kernel 4: output GEMM (A = g_att, B = g_woT), ldmatrix, single-barrier
// multistage, 2 CTA/SM
// ---------------------------------------------------------------------------
__global__ __launch_bounds__(256, 2) void out_kernel(
    const float* __restrict__ bo, float* __restrict__ out) {

    extern __shared__ uint32_t smw[];

    const int n0  = blockIdx.x * 128;
    const int m0  = blockIdx.y * 128;
    const int tid = threadIdx.x;
    const int wid = tid >> 5, lane = tid & 31;
    const int wm = (wid >> 2) * 64;
    const int wn = (wid & 3) * 32;
    const int ln4 = lane >> 2, lc4 = lane & 3;
    const int lx  = lane & 15, lxt = (lane >> 4) << 2;
    const int ly  = lane & 7,  lyt = ((lane >> 3) & 1) << 2;

    auto load_stage = [&](int s, int k0) {
        uint32_t* As = smw + s * STG_W;
        uint32_t* Bs = As + STG_A;
#pragma unroll
        for (int it = 0; it < 4; it++) {
            int idx = tid + it * 256;
            int m = idx >> 3, q = idx & 7;
            cp16(s2u(&As[m * A_ST + q * 4]),
                 &g_att[(size_t)(m0 + m) * kD + k0 + q * 4]);
        }
#pragma unroll
        for (int it = 0; it < 4; it++) {
            int idx = tid + it * 256;
            int n = idx >> 3, q = idx & 7;
            cp16(s2u(&Bs[n * BT_ST + q * 4]),
                 &g_woT[(size_t)(n0 + n) * kD + k0 + q * 4]);
        }
    };

    float acc[4][4][4] = {};

#pragma unroll
    for (int s = 0; s < NSTG - 1; s++) { load_stage(s, s * 32); cp_commit(); }

    const int KT = kD / 32;
    for (int ki = 0; ki < KT; ki++) {
        cp_wait<NSTG - 2>();
        __syncthreads();
        int kn = ki + NSTG - 1;
        if (kn < KT) load_stage(kn % NSTG, kn * 32);
        cp_commit();

        const uint32_t as_b = s2u(smw + (ki % NSTG) * STG_W);
        const uint32_t bs_b = as_b + STG_A * 4;
#pragma unroll
        for (int k8 = 0; k8 < 32; k8 += 8) {
            uint32_t a[4][4], bb[4][2];
#pragma unroll
            for (int mf = 0; mf < 4; mf++)
                ldsm_x4(a[mf], as_b + ((wm + mf * 16 + lx) * A_ST + k8 + lxt) * 4);
#pragma unroll
            for (int nf = 0; nf < 4; nf++)
                ldsm_x2(bb[nf], bs_b + ((wn + nf * 8 + ly) * BT_ST + k8 + lyt) * 4);
#pragma unroll
            for (int mf = 0; mf < 4; mf++)
#pragma unroll
                for (int nf = 0; nf < 4; nf++)
                    mma_tf32(acc[mf][nf], a[mf], bb[nf]);
        }
    }

#pragma unroll
    for (int mf = 0; mf < 4; mf++) {
#pragma unroll
        for (int rp = 0; rp < 2; rp++) {
            const int m = m0 + wm + mf * 16 + ln4 + rp * 8;
#pragma unroll
            for (int nf = 0; nf < 4; nf++) {
                const int n = n0 + wn + nf * 8 + lc4 * 2;
                float v0 = acc[mf][nf][rp * 2 + 0] + bo[n];
                float v1 = acc[mf][nf][rp * 2 + 1] + bo[n + 1];
                *(float2*)&out[(size_t)m * kD + n] = make_float2(v0, v1);
            }
        }
    }
}

// ---------------------------------------------------------------------------
// Launch
// ---------------------------------------------------------------------------
extern "C" void kernel_launch(void* const* d_in, const int* in_sizes, int n_in,
                              void* d_out, int out_size) {
    const float* x  = (const float*)d_in[0];
    const float* rf = (const float*)d_in[2];
    const float* pk = (const float*)d_in[3];
    const float* pv = (const float*)d_in[4];
    const float* Wq = (const float*)d_in[5];
    const float* bq = (const float*)d_in[6];
    const float* Wk = (const float*)d_in[7];
    const float* bk = (const float*)d_in[8];
    const float* Wv = (const float*)d_in[9];
    const float* bv = (const float*)d_in[10];
    const float* Wo = (const float*)d_in[11];
    const float* bo = (const float*)d_in[12];
    float* out = (float*)d_out;

    cudaFuncSetAttribute(qkv_kernel,  cudaFuncAttributeMaxDynamicSharedMemorySize, GEMM_SMEM);
    cudaFuncSetAttribute(out_kernel,  cudaFuncAttributeMaxDynamicSharedMemorySize, GEMM_SMEM);
    cudaFuncSetAttribute(attn_kernel, cudaFuncAttributeMaxDynamicSharedMemorySize, ATTN_SMEM_BYTES);

    cvt_x_kernel<<<(kM * kD / 4 + 255) / 256, 256>>>((const float4*)x);
    cvt_wt_kernel<<<dim3(kNQ / 32,  kD / 32), dim3(32, 8)>>>(Wq, kNQ,  0);
    cvt_wt_kernel<<<dim3(kNKV / 32, kD / 32), dim3(32, 8)>>>(Wk, kNKV, 1);
    cvt_wt_kernel<<<dim3(kNKV / 32, kD / 32), dim3(32, 8)>>>(Wv, kNKV, 2);
    cvt_wt_kernel<<<dim3(kD / 32,   kD / 32), dim3(32, 8)>>>(Wo, kD,   3);
    copy_past_kernel<<<dim3(kHD / 32, kPAST / 32, kB * kG), dim3(32, 8)>>>(pk, pv);
    qkv_kernel<<<dim3(kNTOT / 128, kM / 128), 256, GEMM_SMEM>>>(rf, bq, bk, bv);
    attn_kernel<<<dim3(kLQ / 128, kH, kB), 256, ATTN_SMEM_BYTES>>>();
    out_kernel<<<dim3(kD / 128, kM / 128), 256, GEMM_SMEM>>>(bo, out);
}

// round 17
// speedup vs baseline: 1.7346x; 1.7245x over previous
#include <cuda_runtime.h>
#include <cuda_fp16.h>
#include <math.h>
#include <stdint.h>

// Problem constants
namespace {
constexpr int kB    = 4;
constexpr int kLQ   = 1024;
constexpr int kD    = 2048;
constexpr int kH    = 16;
constexpr int kG    = 4;
constexpr int kHD   = 128;
constexpr int kPAST = 1024;
constexpr int kLK   = 2048;
constexpr int kM    = kB * kLQ;          // 4096
constexpr int kNQ   = kD;                // 2048
constexpr int kNKV  = kG * kHD;          // 512
constexpr int kNTOT = kNQ + 2 * kNKV;    // 3072
constexpr float kScaleL2E = 0.08838834764831845f * 1.4426950408889634f;
}

// Scratch (fp16)
__device__ __half g_q  [kB * kH * kLQ * kHD];   // pre-scaled by kScale*log2e
__device__ __half g_kc [kB * kG * kLK * kHD];   // (b,g,p,d)
__device__ __half g_vt [kB * kG * kHD * kLK];   // (b,g,d,p)  TRANSPOSED
__device__ __half g_att[kB * kLQ * kD];
__device__ __half g_x  [kM * kD];               // [m][k]
__device__ __half g_wqT[kNQ  * kD];             // [n][k] transposed
__device__ __half g_wkT[kNKV * kD];
__device__ __half g_wvT[kNKV * kD];
__device__ __half g_woT[kD   * kD];

// ---------------------------------------------------------------------------
// helpers
// ---------------------------------------------------------------------------
__device__ __forceinline__ float ex2(float x) {
    float r;
    asm("ex2.approx.f32 %0, %1;" : "=f"(r) : "f"(x));
    return r;
}
__device__ __forceinline__ void mma_f16(float* c, const uint32_t* a, const uint32_t* b) {
    asm volatile(
        "mma.sync.aligned.m16n8k16.row.col.f32.f16.f16.f32 "
        "{%0,%1,%2,%3}, {%4,%5,%6,%7}, {%8,%9}, {%0,%1,%2,%3};"
        : "+f"(c[0]), "+f"(c[1]), "+f"(c[2]), "+f"(c[3])
        : "r"(a[0]), "r"(a[1]), "r"(a[2]), "r"(a[3]), "r"(b[0]), "r"(b[1]));
}
__device__ __forceinline__ uint32_t s2u(const void* p) {
    return (uint32_t)__cvta_generic_to_shared(p);
}
__device__ __forceinline__ void cp16(uint32_t saddr, const void* gptr) {
    asm volatile("cp.async.cg.shared.global [%0], [%1], 16;"
                 :: "r"(saddr), "l"(gptr));
}
__device__ __forceinline__ void cp_commit() {
    asm volatile("cp.async.commit_group;" ::: "memory");
}
template <int N>
__device__ __forceinline__ void cp_wait() {
    asm volatile("cp.async.wait_group %0;" :: "n"(N) : "memory");
}
__device__ __forceinline__ void ldsm_x4(uint32_t* r, uint32_t saddr) {
    asm volatile("ldmatrix.sync.aligned.m8n8.x4.shared.b16 {%0,%1,%2,%3}, [%4];"
        : "=r"(r[0]), "=r"(r[1]), "=r"(r[2]), "=r"(r[3]) : "r"(saddr));
}
__device__ __forceinline__ void ldsm_x2(uint32_t* r, uint32_t saddr) {
    asm volatile("ldmatrix.sync.aligned.m8n8.x2.shared.b16 {%0,%1}, [%2];"
        : "=r"(r[0]), "=r"(r[1]) : "r"(saddr));
}

// ---------------------------------------------------------------------------
// Kernel 0a: convert x to fp16 (row-major)
// ---------------------------------------------------------------------------
__global__ void cvt_x_kernel(const float4* __restrict__ x) {
    int i = blockIdx.x * blockDim.x + threadIdx.x;
    if (i < kM * kD / 4) {
        float4 v = x[i];
        ((__half2*)g_x)[i * 2 + 0] = __floats2half2_rn(v.x, v.y);
        ((__half2*)g_x)[i * 2 + 1] = __floats2half2_rn(v.z, v.w);
    }
}

// ---------------------------------------------------------------------------
// Kernel 0b: transpose-convert a weight matrix W[k][n] -> WT[n][k] fp16.
// Destination selected by `which` INSIDE device code.
// ---------------------------------------------------------------------------
__global__ void cvt_wt_kernel(const float* __restrict__ W, int N, int which) {
    __half* WT = (which == 0) ? g_wqT
               : (which == 1) ? g_wkT
               : (which == 2) ? g_wvT : g_woT;
    __shared__ float t[32][33];
    const int n0 = blockIdx.x * 32;
    const int k0 = blockIdx.y * 32;
    const int tx = threadIdx.x, ty = threadIdx.y;
#pragma unroll
    for (int r = 0; r < 4; r++)
        t[ty + r * 8][tx] = W[(size_t)(k0 + ty + r * 8) * N + n0 + tx];
    __syncthreads();
#pragma unroll
    for (int r = 0; r < 4; r++)
        WT[(size_t)(n0 + ty + r * 8) * kD + k0 + tx] = __float2half(t[tx][ty + r * 8]);
}

// ---------------------------------------------------------------------------
// Kernel 1: copy past K (straight) + past V (transposed) into caches
// ---------------------------------------------------------------------------
__global__ void copy_past_kernel(const float* __restrict__ pk,
                                 const float* __restrict__ pv) {
    __shared__ float t[32][33];
    const int bg = blockIdx.z;
    const int p0 = blockIdx.y * 32;
    const int d0 = blockIdx.x * 32;
    const int tx = threadIdx.x, ty = threadIdx.y;
#pragma unroll
    for (int r = 0; r < 4; r++) {
        int p = p0 + ty + r * 8;
        size_t src = ((size_t)bg * kPAST + p) * kHD + d0 + tx;
        g_kc[((size_t)bg * kLK + p) * kHD + d0 + tx] = __float2half(pk[src]);
        t[ty + r * 8][tx] = pv[src];
    }
    __syncthreads();
#pragma unroll
    for (int r = 0; r < 4; r++) {
        int d = d0 + ty + r * 8;
        g_vt[((size_t)bg * kHD + d) * kLK + p0 + tx] = __float2half(t[tx][ty + r * 8]);
    }
}

// ---------------------------------------------------------------------------
// GEMM pipeline: 128x128x32(halves), 3-stage cp.async, 2 CTAs/SM, m16n8k16.
// Strides in halves: 40 == 8*5 (odd s) -> ldmatrix conflict-free.
// ---------------------------------------------------------------------------
constexpr int A_ST  = 40;               // halves
constexpr int BT_ST = 40;
constexpr int STG_A = 128 * A_ST;       // halves
constexpr int STG_B = 128 * BT_ST;
constexpr int STG_W = STG_A + STG_B;    // 10240 halves = 20480 B
constexpr int NSTG  = 3;
constexpr int GEMM_SMEM = NSTG * STG_W * 2;   // 61,440 B (x2 CTAs = 123 KB)

// ---------------------------------------------------------------------------
// Kernel 2: QKV projection GEMM + bias + RoPE + fp16 scatter
// ---------------------------------------------------------------------------
__global__ __launch_bounds__(256, 2) void qkv_kernel(
    const float* __restrict__ rf,
    const float* __restrict__ bq, const float* __restrict__ bk,
    const float* __restrict__ bv) {

    extern __shared__ __half smh[];

    const int n0  = blockIdx.x * 128;
    const int m0  = blockIdx.y * 128;
    const int tid = threadIdx.x;
    const int wid = tid >> 5, lane = tid & 31;
    const int wm = (wid >> 2) * 64;
    const int wn = (wid & 3) * 32;
    const int ln4 = lane >> 2, lc4 = lane & 3;
    const int lx  = lane & 15, lxt8 = (lane >> 4) << 3;          // A frag addr
    const int ly  = lane & 7,  lyt8 = ((lane >> 3) & 1) << 3;    // B frag addr

    const __half* WT; const float* bias; int nloc; int seg;
    if (n0 < kNQ)              { WT = g_wqT; bias = bq; nloc = n0;              seg = 0; }
    else if (n0 < kNQ + kNKV)  { WT = g_wkT; bias = bk; nloc = n0 - kNQ;        seg = 1; }
    else                       { WT = g_wvT; bias = bv; nloc = n0 - kNQ - kNKV; seg = 2; }

    // loaders: 128 rows x 32 halves = 4 chunks(8h) per row = 512 cp16 -> 2 iters
    auto load_stage = [&](int s, int k0) {
        __half* As = smh + s * STG_W;
        __half* Bs = As + STG_A;
#pragma unroll
        for (int it = 0; it < 2; it++) {
            int idx = tid + it * 256;
            int m = idx >> 2, q = idx & 3;
            cp16(s2u(&As[m * A_ST + q * 8]),
                 &g_x[(size_t)(m0 + m) * kD + k0 + q * 8]);
        }
#pragma unroll
        for (int it = 0; it < 2; it++) {
            int idx = tid + it * 256;
            int n = idx >> 2, q = idx & 3;
            cp16(s2u(&Bs[n * BT_ST + q * 8]),
                 &WT[(size_t)(nloc + n) * kD + k0 + q * 8]);
        }
    };

    float acc[4][4][4] = {};

#pragma unroll
    for (int s = 0; s < NSTG; s++) { load_stage(s, s * 32); cp_commit(); }

    const int KT = kD / 32;   // 64 iterations, BK=32 halves
    for (int ki = 0; ki < KT; ki++) {
        cp_wait<NSTG - 1>();
        __syncthreads();
        const uint32_t as_b = s2u(smh + (ki % NSTG) * STG_W);
        const uint32_t bs_b = as_b + STG_A * 2;
#pragma unroll
        for (int k16 = 0; k16 < 32; k16 += 16) {
            uint32_t a[4][4], bb[4][2];
#pragma unroll
            for (int mf = 0; mf < 4; mf++)
                ldsm_x4(a[mf], as_b + ((wm + mf * 16 + lx) * A_ST + k16 + lxt8) * 2);
#pragma unroll
            for (int nf = 0; nf < 4; nf++)
                ldsm_x2(bb[nf], bs_b + ((wn + nf * 8 + ly) * BT_ST + k16 + lyt8) * 2);
#pragma unroll
            for (int mf = 0; mf < 4; mf++)
#pragma unroll
                for (int nf = 0; nf < 4; nf++)
                    mma_f16(acc[mf][nf], a[mf], bb[nf]);
        }
        __syncthreads();
        int kn = ki + NSTG;
        if (kn < KT) load_stage(ki % NSTG, kn * 32);
        cp_commit();
    }

    // Epilogue: bias + RoPE + fp16 scatter
#pragma unroll
    for (int mf = 0; mf < 4; mf++) {
#pragma unroll
        for (int rp = 0; rp < 2; rp++) {
            const int m = m0 + wm + mf * 16 + ln4 + rp * 8;
            const int b = m >> 10;
            const int t = m & (kLQ - 1);
#pragma unroll
            for (int nf = 0; nf < 4; nf++) {
                const int n = nloc + wn + nf * 8 + lc4 * 2;
                float v0 = acc[mf][nf][rp * 2 + 0] + bias[n];
                float v1 = acc[mf][nf][rp * 2 + 1] + bias[n + 1];
                const int d = n & 127;
                if (seg == 0) {
                    const int h = n >> 7;
                    float sn, cs; sincosf(rf[t * (kHD / 2) + (d >> 1)], &sn, &cs);
                    float r0 = v0 * cs - v1 * sn;
                    float r1 = v0 * sn + v1 * cs;
                    __half* dst = &g_q[((size_t)((b * kH + h) * kLQ + t) * kHD) + d];
                    *(__half2*)dst = __floats2half2_rn(r0 * kScaleL2E, r1 * kScaleL2E);
                } else if (seg == 1) {
                    const int g = n >> 7;
                    float sn, cs; sincosf(rf[t * (kHD / 2) + (d >> 1)], &sn, &cs);
                    float r0 = v0 * cs - v1 * sn;
                    float r1 = v0 * sn + v1 * cs;
                    __half* dst = &g_kc[((size_t)((b * kG + g) * kLK + kPAST + t) * kHD) + d];
                    *(__half2*)dst = __floats2half2_rn(r0, r1);
                } else {
                    const int g = n >> 7;
                    size_t base = ((size_t)(b * kG + g) * kHD + d) * kLK + kPAST + t;
                    g_vt[base]       = __float2half(v0);
                    g_vt[base + kLK] = __float2half(v1);
                }
            }
        }
    }
}

// ---------------------------------------------------------------------------
// Kernel 3: flash attention — R12 structure, fp16 m16n8k16, max-free softmax.
// BQ=128, BK=64; 8 warps (4m x 2n); 2 barriers per K-tile.
// Strides (halves): 136 = 8*17, 72 = 8*9 (odd s) -> ldmatrix conflict-free.
// ---------------------------------------------------------------------------
constexpr int QS_ST = 136;   // [t][d]
constexpr int KK_ST = 136;   // [key][d]
constexpr int VT_ST = 72;    // [d][key]
constexpr int PS_ST = 72;    // [row][key]
constexpr int ATTN_HALVES = 128 * QS_ST + 64 * KK_ST + 128 * VT_ST + 128 * PS_ST;
constexpr int ATTN_SMEM_BYTES = ATTN_HALVES * 2 + 2 * 128 * 4;   // 90,112 B

__global__ __launch_bounds__(256, 1) void attn_kernel() {
    extern __shared__ __half smh[];
    __half* Qs = smh;
    __half* Kb = Qs + 128 * QS_ST;
    __half* Vt = Kb + 64 * KK_ST;
    __half* Ps = Vt + 128 * VT_ST;
    float*  red = (float*)(Ps + 128 * PS_ST);   // [2 wn2][128 rows]

    const int qb = blockIdx.x;
    const int h  = blockIdx.y;
    const int b  = blockIdx.z;
    const int g  = h >> 2;
    const int t0 = qb * 128;
    const int tid = threadIdx.x;
    const int wid = tid >> 5, lane = tid & 31;
    const int wm2 = wid >> 1;
    const int wn2 = wid & 1;
    const int arow = wm2 * 32;
    const int ln4 = lane >> 2, lc4 = lane & 3;
    const int lx  = lane & 15, lxt8 = (lane >> 4) << 3;
    const int ly  = lane & 7,  lyt8 = ((lane >> 3) & 1) << 3;

    const uint32_t qs_b = s2u(Qs), kb_b = s2u(Kb), vt_b = s2u(Vt), ps_b = s2u(Ps);

    const __half* qbase  = g_q  + ((size_t)(b * kH + h) * kLQ + t0) * kHD;
    const __half* kbase  = g_kc + (size_t)(b * kG + g) * kLK * kHD;
    const __half* vtbase = g_vt + (size_t)(b * kG + g) * kHD * kLK;

    // Prologue loaders:
    // Q: 128 rows x 128 halves = 16 chunks(8h)/row = 2048 cp16 -> 8 iters
    // K: 64 rows x 128 halves  = 1024 cp16 -> 4 iters
#pragma unroll
    for (int it = 0; it < 8; it++) {
        int idx = tid + it * 256;
        int t = idx >> 4, q = idx & 15;
        cp16(qs_b + (t * QS_ST + q * 8) * 2, &qbase[(size_t)t * kHD + q * 8]);
    }
#pragma unroll
    for (int it = 0; it < 4; it++) {
        int idx = tid + it * 256;
        int key = idx >> 4, q = idx & 15;
        cp16(kb_b + (key * KK_ST + q * 8) * 2, &kbase[(size_t)key * kHD + q * 8]);
    }
    cp_commit();

    float oacc[2][8][4] = {};
    float l_i[4] = {0.f, 0.f, 0.f, 0.f};

    const int ntiles = (kPAST + t0) / 64 + 2;

    for (int kt = 0; kt < ntiles; kt++) {
        const int k0 = kt * 64;
        cp_wait<0>();
        __syncthreads();       // K(kt) visible; prev O-mma done with Vt

        // V(kt): 128 d-rows x 64 keys halves = 8 chunks/row = 1024 cp16 -> 4 iters
#pragma unroll
        for (int it = 0; it < 4; it++) {
            int idx = tid + it * 256;
            int row = idx >> 3, c = (idx & 7) << 3;
            cp16(vt_b + (row * VT_ST + c) * 2,
                 &vtbase[(size_t)row * kLK + k0 + c]);
        }
        cp_commit();

        // S = Q.K^T  — warp tile m32 x n32, k=128 (8 steps of k16)
        float sacc[2][4][4] = {};
#pragma unroll
        for (int k8 = 0; k8 < 8; k8++) {
            const int d0 = k8 * 16;
            uint32_t a[2][4], bb[4][2];
#pragma unroll
            for (int mf2 = 0; mf2 < 2; mf2++)
                ldsm_x4(a[mf2], qs_b + ((arow + mf2 * 16 + lx) * QS_ST + d0 + lxt8) * 2);
#pragma unroll
            for (int nf = 0; nf < 4; nf++)
                ldsm_x2(bb[nf], kb_b + ((wn2 * 32 + nf * 8 + ly) * KK_ST + d0 + lyt8) * 2);
#pragma unroll
            for (int mf2 = 0; mf2 < 2; mf2++)
#pragma unroll
                for (int nf = 0; nf < 4; nf++)
                    mma_f16(sacc[mf2][nf], a[mf2], bb[nf]);
        }

        // causal mask near diagonal
        if (k0 + 63 > kPAST + t0) {
#pragma unroll
            for (int mf2 = 0; mf2 < 2; mf2++) {
                const int qpos0 = kPAST + t0 + arow + mf2 * 16 + ln4;
#pragma unroll
                for (int nf = 0; nf < 4; nf++)
#pragma unroll
                    for (int j = 0; j < 2; j++) {
                        int kpos = k0 + wn2 * 32 + nf * 8 + lc4 * 2 + j;
                        if (kpos > qpos0)     sacc[mf2][nf][j]     = -1e30f;
                        if (kpos > qpos0 + 8) sacc[mf2][nf][2 + j] = -1e30f;
                    }
            }
        }

        // ---- max-free softmax: p = ex2(s), local l accumulate, store P ----
#pragma unroll
        for (int mf2 = 0; mf2 < 2; mf2++)
#pragma unroll
            for (int nf = 0; nf < 4; nf++) {
                float p0 = ex2(sacc[mf2][nf][0]);
                float p1 = ex2(sacc[mf2][nf][1]);
                float p2 = ex2(sacc[mf2][nf][2]);
                float p3 = ex2(sacc[mf2][nf][3]);
                l_i[mf2 * 2 + 0] += p0 + p1;
                l_i[mf2 * 2 + 1] += p2 + p3;
                int col = wn2 * 32 + nf * 8 + lc4 * 2;
                *(__half2*)&Ps[(arow + mf2 * 16 + ln4) * PS_ST + col] =
                    __floats2half2_rn(p0, p1);
                *(__half2*)&Ps[(arow + mf2 * 16 + ln4 + 8) * PS_ST + col] =
                    __floats2half2_rn(p2, p3);
            }

        cp_wait<0>();          // V(kt) complete
        __syncthreads();       // V + Ps visible; all Kb reads retired

        // prefetch K(kt+1): 64 rows x 16 chunks -> 4 iters
        if (kt + 1 < ntiles) {
            int kn0 = k0 + 64;
#pragma unroll
            for (int it = 0; it < 4; it++) {
                int idx = tid + it * 256;
                int key = idx >> 4, q = idx & 15;
                cp16(kb_b + (key * KK_ST + q * 8) * 2,
                     &kbase[(size_t)(kn0 + key) * kHD + q * 8]);
            }
        }
        cp_commit();

        // O += P.V — warp tile m32 x n64, k=64 (4 steps of k16)
#pragma unroll
        for (int kk8 = 0; kk8 < 4; kk8++) {
            const int kk0 = kk8 * 16;
            uint32_t a[2][4], bb[8][2];
#pragma unroll
            for (int mf2 = 0; mf2 < 2; mf2++)
                ldsm_x4(a[mf2], ps_b + ((arow + mf2 * 16 + lx) * PS_ST + kk0 + lxt8) * 2);
#pragma unroll
            for (int nf = 0; nf < 8; nf++)
                ldsm_x2(bb[nf], vt_b + ((wn2 * 64 + nf * 8 + ly) * VT_ST + kk0 + lyt8) * 2);
#pragma unroll
            for (int mf2 = 0; mf2 < 2; mf2++)
#pragma unroll
                for (int nf = 0; nf < 8; nf++)
                    mma_f16(oacc[mf2][nf], a[mf2], bb[nf]);
        }
    }

    // ---- epilogue: reduce l across lanes + key-half warps, then store ----
#pragma unroll
    for (int i = 0; i < 4; i++) {
        l_i[i] += __shfl_xor_sync(0xffffffffu, l_i[i], 1);
        l_i[i] += __shfl_xor_sync(0xffffffffu, l_i[i], 2);
    }
    if (lc4 == 0) {
#pragma unroll
        for (int i = 0; i < 4; i++)
            red[wn2 * 128 + arow + (i >> 1) * 16 + (i & 1) * 8 + ln4] = l_i[i];
    }
    __syncthreads();
#pragma unroll
    for (int i = 0; i < 4; i++) {
        int row = arow + (i >> 1) * 16 + (i & 1) * 8 + ln4;
        l_i[i] += red[(wn2 ^ 1) * 128 + row];
    }

#pragma unroll
    for (int mf2 = 0; mf2 < 2; mf2++) {
        const float inv0 = 1.f / l_i[mf2 * 2];
        const float inv1 = 1.f / l_i[mf2 * 2 + 1];
        const int rowA = t0 + arow + mf2 * 16 + ln4;
        __half* dA = &g_att[((size_t)(b * kLQ + rowA)) * kD + h * kHD];
        __half* dB = &g_att[((size_t)(b * kLQ + rowA + 8)) * kD + h * kHD];
#pragma unroll
        for (int nf = 0; nf < 8; nf++) {
            int col = wn2 * 64 + nf * 8 + lc4 * 2;
            *(__half2*)&dA[col] = __floats2half2_rn(oacc[mf2][nf][0] * inv0,
                                                    oacc[mf2][nf][1] * inv0);
            *(__half2*)&dB[col] = __floats2half2_rn(oacc[mf2][nf][2] * inv1,
                                                    oacc[mf2][nf][3] * inv1);
        }
    }
}

// ---------------------------------------------------------------------------
// Kernel 4: output GEMM (A = g_att, B = g_woT, fp16), m16n8k16, 2 CTA/SM
// ---------------------------------------------------------------------------
__global__ __launch_bounds__(256, 2) void out_kernel(
    const float* __restrict__ bo, float* __restrict__ out) {

    extern __shared__ __half smh[];

    const int n0  = blockIdx.x * 128;
    const int m0  = blockIdx.y * 128;
    const int tid = threadIdx.x;
    const int wid = tid >> 5, lane = tid & 31;
    const int wm = (wid >> 2) * 64;
    const int wn = (wid & 3) * 32;
    const int ln4 = lane >> 2, lc4 = lane & 3;
    const int lx  = lane & 15, lxt8 = (lane >> 4) << 3;
    const int ly  = lane & 7,  lyt8 = ((lane >> 3) & 1) << 3;

    auto load_stage = [&](int s, int k0) {
        __half* As = smh + s * STG_W;
        __half* Bs = As + STG_A;
#pragma unroll
        for (int it = 0; it < 2; it++) {
            int idx = tid + it * 256;
            int m = idx >> 2, q = idx & 3;
            cp16(s2u(&As[m * A_ST + q * 8]),
                 &g_att[(size_t)(m0 + m) * kD + k0 + q * 8]);
        }
#pragma unroll
        for (int it = 0; it < 2; it++) {
            int idx = tid + it * 256;
            int n = idx >> 2, q = idx & 3;
            cp16(s2u(&Bs[n * BT_ST + q * 8]),
                 &g_woT[(size_t)(n0 + n) * kD + k0 + q * 8]);
        }
    };

    float acc[4][4][4] = {};

#pragma unroll
    for (int s = 0; s < NSTG; s++) { load_stage(s, s * 32); cp_commit(); }

    const int KT = kD / 32;
    for (int ki = 0; ki < KT; ki++) {
        cp_wait<NSTG - 1>();
        __syncthreads();
        const uint32_t as_b = s2u(smh + (ki % NSTG) * STG_W);
        const uint32_t bs_b = as_b + STG_A * 2;
#pragma unroll
        for (int k16 = 0; k16 < 32; k16 += 16) {
            uint32_t a[4][4], bb[4][2];
#pragma unroll
            for (int mf = 0; mf < 4; mf++)
                ldsm_x4(a[mf], as_b + ((wm + mf * 16 + lx) * A_ST + k16 + lxt8) * 2);
#pragma unroll
            for (int nf = 0; nf < 4; nf++)
                ldsm_x2(bb[nf], bs_b + ((wn + nf * 8 + ly) * BT_ST + k16 + lyt8) * 2);
#pragma unroll
            for (int mf = 0; mf < 4; mf++)
#pragma unroll
                for (int nf = 0; nf < 4; nf++)
                    mma_f16(acc[mf][nf], a[mf], bb[nf]);
        }
        __syncthreads();
        int kn = ki + NSTG;
        if (kn < KT) load_stage(ki % NSTG, kn * 32);
        cp_commit();
    }

#pragma unroll
    for (int mf = 0; mf < 4; mf++) {
#pragma unroll
        for (int rp = 0; rp < 2; rp++) {
            const int m = m0 + wm + mf * 16 + ln4 + rp * 8;
#pragma unroll
            for (int nf = 0; nf < 4; nf++) {
                const int n = n0 + wn + nf * 8 + lc4 * 2;
                float v0 = acc[mf][nf][rp * 2 + 0] + bo[n];
                float v1 = acc[mf][nf][rp * 2 + 1] + bo[n + 1];
                *(float2*)&out[(size_t)m * kD + n] = make_float2(v0, v1);
            }
        }
    }
}

// ---------------------------------------------------------------------------
// Launch
// ---------------------------------------------------------------------------
extern "C" void kernel_launch(void* const* d_in, const int* in_sizes, int n_in,
                              void* d_out, int out_size) {
    const float* x  = (const float*)d_in[0];
    const float* rf = (const float*)d_in[2];
    const float* pk = (const float*)d_in[3];
    const float* pv = (const float*)d_in[4];
    const float* Wq = (const float*)d_in[5];
    const float* bq = (const float*)d_in[6];
    const float* Wk = (const float*)d_in[7];
    const float* bk = (const float*)d_in[8];
    const float* Wv = (const float*)d_in[9];
    const float* bv = (const float*)d_in[10];
    const float* Wo = (const float*)d_in[11];
    const float* bo = (const float*)d_in[12];
    float* out = (float*)d_out;

    cudaFuncSetAttribute(qkv_kernel,  cudaFuncAttributeMaxDynamicSharedMemorySize, GEMM_SMEM);
    cudaFuncSetAttribute(out_kernel,  cudaFuncAttributeMaxDynamicSharedMemorySize, GEMM_SMEM);
    cudaFuncSetAttribute(attn_kernel, cudaFuncAttributeMaxDynamicSharedMemorySize, ATTN_SMEM_BYTES);

    cvt_x_kernel<<<(kM * kD / 4 + 255) / 256, 256>>>((const float4*)x);
    cvt_wt_kernel<<<dim3(kNQ / 32,  kD / 32), dim3(32, 8)>>>(Wq, kNQ,  0);
    cvt_wt_kernel<<<dim3(kNKV / 32, kD / 32), dim3(32, 8)>>>(Wk, kNKV, 1);
    cvt_wt_kernel<<<dim3(kNKV / 32, kD / 32), dim3(32, 8)>>>(Wv, kNKV, 2);
    cvt_wt_kernel<<<dim3(kD / 32,   kD / 32), dim3(32, 8)>>>(Wo, kD,   3);
    copy_past_kernel<<<dim3(kHD / 32, kPAST / 32, kB * kG), dim3(32, 8)>>>(pk, pv);
    qkv_kernel<<<dim3(kNTOT / 128, kM / 128), 256, GEMM_SMEM>>>(rf, bq, bk, bv);
    attn_kernel<<<dim3(kLQ / 128, kH, kB), 256, ATTN_SMEM_BYTES>>>();
    out_kernel<<<dim3(kD / 128, kM / 128), 256, GEMM_SMEM>>>(bo, out);
}